// round 7
// baseline (speedup 1.0000x reference)
#include <cuda_runtime.h>
#include <stdint.h>
#include <math_constants.h>

// ProbSparse attention (Informer) — B=4, L=2048, H=8, D=64, U_part=u=40.
// Layout of all tensors: (B, L, H, D) row-major.

#define BB 4
#define LL 2048
#define HH 8
#define DD 64
#define UU 40
#define SS 40
#define BH (BB*HH)       // 32
#define NEL (LL*SS)      // 81920
#define NCHB 4           // key chunks for sampled-score bucketing
#define CKEY 512         // keys per bucket chunk
#define NCH 16           // key chunks for split-K attention
#define CH  128
#define SCALE 0.125f

__device__ __align__(16) int      g_idx[NEL];
__device__ __align__(16) uint16_t g_cnt16[NCHB*LL];
__device__ __align__(16) uint16_t g_pairs2[NCHB*LL*SS];   // [c][l][<=40]
__device__ __align__(16) float    g_pM[NCHB*BH*LL];
__device__ __align__(16) float    g_pS[NCHB*BH*LL];
__device__ __align__(16) int      g_Mtop[BH*UU];
__device__ __align__(16) float    g_Vmean[BH*DD];
__device__ __align__(16) float    g_pm[BH*UU*NCH];
__device__ __align__(16) float    g_ps[BH*UU*NCH];
__device__ __align__(16) float    g_pa[BH*UU*NCH*DD];

// ---------------------------------------------------------------------------
// Threefry-2x32-20, constexpr-evaluable.
// ---------------------------------------------------------------------------
__host__ __device__ constexpr uint64_t tf2x32(uint32_t k0, uint32_t k1,
                                              uint32_t c0, uint32_t c1) {
    uint32_t ks0 = k0, ks1 = k1, ks2 = k0 ^ k1 ^ 0x1BD11BDAu;
    uint32_t x0 = c0 + ks0, x1 = c1 + ks1;
    const int rotA[4] = {13, 15, 26, 6};
    const int rotB[4] = {17, 29, 16, 24};
    for (int g = 0; g < 5; g++) {
        const int* rot = (g & 1) ? rotB : rotA;
        for (int r = 0; r < 4; r++) {
            x0 += x1;
            x1 = (x1 << rot[r]) | (x1 >> (32 - rot[r]));
            x1 ^= x0;
        }
        uint32_t inj0 = 0, inj1 = 0;
        switch (g) {
            case 0: inj0 = ks1; inj1 = ks2 + 1u; break;
            case 1: inj0 = ks2; inj1 = ks0 + 2u; break;
            case 2: inj0 = ks0; inj1 = ks1 + 3u; break;
            case 3: inj0 = ks1; inj1 = ks2 + 4u; break;
            case 4: inj0 = ks2; inj1 = ks0 + 5u; break;
        }
        x0 += inj0; x1 += inj1;
    }
    return ((uint64_t)x0 << 32) | (uint64_t)x1;
}

constexpr uint64_t K2PAIR = tf2x32(0u, 42u, 0u, 1u);
#define K2_HI ((uint32_t)(K2PAIR >> 32))
#define K2_LO ((uint32_t)(K2PAIR & 0xffffffffu))

// ---------------------------------------------------------------------------
// K1: sampled indices (fold-xor threefry under split key) & 2047.
// Also zeroes g_Vmean.
// ---------------------------------------------------------------------------
__global__ void k_rng() {
    int i = blockIdx.x * blockDim.x + threadIdx.x;
    if (i < BH * DD) g_Vmean[i] = 0.f;
    if (i >= NEL) return;
    uint64_t y = tf2x32(K2_HI, K2_LO, 0u, (uint32_t)i);
    uint32_t bits = (uint32_t)(y >> 32) ^ (uint32_t)(y & 0xffffffffu);
    g_idx[i] = (int)(bits & (LL - 1));
}

// ---------------------------------------------------------------------------
// K1b: per-(chunk,l) counts. One thread per l, MLP-40 unrolled loads.
// ---------------------------------------------------------------------------
__global__ void k_count() {
    int l = blockIdx.x * 256 + threadIdx.x;
    if (l >= LL) return;
    int v[SS];
#pragma unroll
    for (int s = 0; s < SS; s++) v[s] = g_idx[l * SS + s] >> 9;
    int c0 = 0, c1 = 0, c2 = 0, c3 = 0;
#pragma unroll
    for (int s = 0; s < SS; s++) {
        c0 += (v[s] == 0); c1 += (v[s] == 1); c2 += (v[s] == 2); c3 += (v[s] == 3);
    }
    g_cnt16[0 * LL + l] = (uint16_t)c0; g_cnt16[1 * LL + l] = (uint16_t)c1;
    g_cnt16[2 * LL + l] = (uint16_t)c2; g_cnt16[3 * LL + l] = (uint16_t)c3;
}

// ---------------------------------------------------------------------------
// K1c: fully parallel stable scatter into fixed-capacity buckets.
// Thread per (l,s): rank = #{s'<s : same chunk}; row data is L1-resident.
// ---------------------------------------------------------------------------
__global__ void k_rank() {
    int t = blockIdx.x * 256 + threadIdx.x;
    if (t >= NEL) return;
    int l = t / SS, s = t - l * SS;
    int my = g_idx[l * SS + s];
    int c = my >> 9;
    int rank = 0;
    for (int s2 = 0; s2 < s; s2++)
        rank += ((g_idx[l * SS + s2] >> 9) == c);
    g_pairs2[(c * LL + l) * SS + rank] = (uint16_t)(my & (CKEY - 1));
}

// ---------------------------------------------------------------------------
// K2: sampled-score partials. Block = (bh, chunk) -> 128 blocks, 512 threads,
// 132KB dynamic smem (forces 1 block/SM). The 512-row K chunk (128KB) and
// all 2048 per-l counts (4KB) are staged in smem. Octet scheme: each octet
// (8 lanes) computes one sample dot (2x LDS.128/lane, phase = quarter-warp =
// one octet = contiguous 128B -> conflict-free); 4 samples/iter, 3 shfl per 4.
// ---------------------------------------------------------------------------
#define SMK (CKEY*DD)                       // 32768 floats = 128KB
#define SAMPLE_SH_BYTES (SMK*4 + LL*2)      // + counts

__global__ void __launch_bounds__(512) k_sampleM2(const float* __restrict__ Q,
                                                  const float* __restrict__ K) {
    int c  = blockIdx.x & (NCHB - 1);
    int bh = blockIdx.x >> 2;
    int b = bh >> 3, h = bh & 7;
    int lane = threadIdx.x & 31, wid = threadIdx.x >> 5;
    int oct = lane >> 3, oj = lane & 7;

    extern __shared__ float sk[];                 // [512][64]
    uint16_t* scnt = (uint16_t*)(sk + SMK);       // [2048]

    // stage K chunk: 512 rows x 256B, coalesced (16 threads per row).
    const float* Kc = K + ((size_t)(b * LL + c * CKEY) * HH + h) * DD;
    for (int i = threadIdx.x; i < CKEY * (DD / 4); i += 512) {
        int r = i >> 4, q4 = i & 15;
        float4 v = __ldcg((const float4*)(Kc + (size_t)r * (HH * DD) + q4 * 4));
        *(float4*)(sk + r * DD + q4 * 4) = v;
    }
    for (int i = threadIdx.x; i < LL; i += 512)
        scnt[i] = g_cnt16[c * LL + i];
    __syncthreads();

    for (int l = wid; l < LL; l += 16) {
        int cnt = (int)scnt[l];
        const float* qrow = Q + ((size_t)(b * LL + l) * HH + h) * DD;
        float4 qa = __ldcg((const float4*)(qrow + oj * 8));
        float4 qb = __ldcg((const float4*)(qrow + oj * 8 + 4));
        const uint16_t* pr = g_pairs2 + (c * LL + l) * SS;

        float mx = -CUDART_INF_F, sm = 0.f;
        for (int t0 = 0; t0 < cnt; t0 += 4) {
            int myt = t0 + oct;
            int kloc = (myt < cnt) ? (int)pr[myt] : 0;
            const float* krow = sk + kloc * DD;
            float4 ka = *(const float4*)(krow + oj * 8);
            float4 kb = *(const float4*)(krow + oj * 8 + 4);
            float p = qa.x * ka.x + qa.y * ka.y + qa.z * ka.z + qa.w * ka.w
                    + qb.x * kb.x + qb.y * kb.y + qb.z * kb.z + qb.w * kb.w;
            p += __shfl_xor_sync(0xffffffffu, p, 1);
            p += __shfl_xor_sync(0xffffffffu, p, 2);
            p += __shfl_xor_sync(0xffffffffu, p, 4);
            if (myt < cnt) { mx = fmaxf(mx, p); sm += p; }
        }
        mx = fmaxf(mx, __shfl_xor_sync(0xffffffffu, mx, 8));
        mx = fmaxf(mx, __shfl_xor_sync(0xffffffffu, mx, 16));
        sm = sm + __shfl_xor_sync(0xffffffffu, sm, 8);
        sm = sm + __shfl_xor_sync(0xffffffffu, sm, 16);
        if (lane == 0) {
            g_pM[(c * BH + bh) * LL + l] = mx;
            g_pS[(c * BH + bh) * LL + l] = sm;
        }
    }
}

// ---------------------------------------------------------------------------
// K3: merge chunk partials -> M, then exact top-40 per (b,h) via bitonic sort
// of (value,index), comparator (v desc, idx asc). 512 threads.
// ---------------------------------------------------------------------------
__global__ void k_topk() {
    int bh = blockIdx.x;
    __shared__ float sv[LL];
    __shared__ int   si[LL];
    int t = threadIdx.x;
    for (int i = t; i < LL; i += 512) {
        float m0 = g_pM[(0 * BH + bh) * LL + i];
        float m1 = g_pM[(1 * BH + bh) * LL + i];
        float m2 = g_pM[(2 * BH + bh) * LL + i];
        float m3 = g_pM[(3 * BH + bh) * LL + i];
        float mm = fmaxf(fmaxf(m0, m1), fmaxf(m2, m3));
        float s  = ((g_pS[(0 * BH + bh) * LL + i]  + g_pS[(1 * BH + bh) * LL + i])
                  +  g_pS[(2 * BH + bh) * LL + i]) + g_pS[(3 * BH + bh) * LL + i];
        sv[i] = mm - s * (1.0f / (float)LL);
        si[i] = i;
    }
    __syncthreads();
    for (int k = 2; k <= LL; k <<= 1) {
        for (int j = k >> 1; j > 0; j >>= 1) {
            for (int i = t; i < LL; i += 512) {
                int p = i ^ j;
                if (p > i) {
                    bool asc = (i & k) == 0;
                    float va = sv[i], vp = sv[p];
                    int   ia = si[i], ip = si[p];
                    bool pre = (vp > va) || (vp == va && ip < ia);
                    if (asc == pre) {
                        sv[i] = vp; sv[p] = va;
                        si[i] = ip; si[p] = ia;
                    }
                }
            }
            __syncthreads();
        }
    }
    if (t < UU) g_Mtop[bh * UU + t] = si[t];
}

// ---------------------------------------------------------------------------
// K4: V_mean partials; 1024 blocks (bh x 32 L-chunks of 64), atomicAdd merge.
// ---------------------------------------------------------------------------
__global__ void k_vmean(const float* __restrict__ V) {
    int blk = blockIdx.x;
    int bh = blk >> 5, chn = blk & 31;
    int b = bh >> 3, h = bh & 7;
    int t = threadIdx.x;
    int d = t & 63, sub = t >> 6;
    float s = 0.f;
#pragma unroll 16
    for (int i = 0; i < 16; i++) {
        int l = chn * 64 + sub + i * 4;
        s += V[(((size_t)(b * LL + l)) * HH + h) * DD + d];
    }
    __shared__ float red[256];
    red[t] = s;
    __syncthreads();
    if (t < 64) {
        float tot = red[t] + red[t + 64] + red[t + 128] + red[t + 192];
        atomicAdd(&g_Vmean[bh * DD + t], tot * (1.0f / (float)LL));
    }
}

// ---------------------------------------------------------------------------
// K5: out[b,l,h,:] = V_mean[b,h,:] for all l.
// ---------------------------------------------------------------------------
__global__ void k_fill(float* __restrict__ out) {
    int i = blockIdx.x * blockDim.x + threadIdx.x;
    if (i >= BB * LL * HH * (DD / 4)) return;
    int q4  = i & 15;
    int row = i >> 4;
    int h = row & 7;
    int b = row >> 14;
    float4 vm = reinterpret_cast<const float4*>(g_Vmean)[((b << 3) + h) * (DD / 4) + q4];
    reinterpret_cast<float4*>(out)[i] = vm;
}

// ---------------------------------------------------------------------------
// K6a: split-K attention partials. Block = (b,h, key-chunk of 128), 256 thr.
// ---------------------------------------------------------------------------
#define QS_PITCH 66
#define KS_PITCH 66
#define S_PITCH  130
#define SH_FLOATS (UU*QS_PITCH + CH*KS_PITCH + CH*KS_PITCH + UU*S_PITCH)
#define SH_BYTES  (SH_FLOATS*4 + UU*4)

__global__ void k_attn_part(const float* __restrict__ Q, const float* __restrict__ K,
                            const float* __restrict__ V) {
    int ch = blockIdx.x & (NCH - 1);
    int bh = blockIdx.x >> 4;
    int b = bh >> 3, h = bh & 7;
    int t = threadIdx.x;

    extern __shared__ float sh[];
    float* Qs = sh;                          // [40][66]
    float* Ks = Qs + UU * QS_PITCH;          // [128][66]
    float* Vs = Ks + CH * KS_PITCH;          // [128][66]
    float* S  = Vs + CH * KS_PITCH;          // [40][130]
    int* sidx = (int*)(S + UU * S_PITCH);    // [40]

    if (t < UU) sidx[t] = g_Mtop[bh * UU + t];
    __syncthreads();

    for (int i = t; i < UU * (DD / 4); i += 256) {
        int j = i >> 4, q4 = i & 15;
        float4 v = *(const float4*)(Q + (((size_t)(b * LL + sidx[j])) * HH + h) * DD + q4 * 4);
        float* dst = Qs + j * QS_PITCH + q4 * 4;
        dst[0] = v.x; dst[1] = v.y; dst[2] = v.z; dst[3] = v.w;
    }
    int k0 = ch * CH;
    for (int i = t; i < CH * (DD / 4); i += 256) {
        int r = i >> 4, q4 = i & 15;
        size_t base = (((size_t)(b * LL + k0 + r)) * HH + h) * DD + q4 * 4;
        float4 kv = *(const float4*)(K + base);
        float4 vv = *(const float4*)(V + base);
        float* dk = Ks + r * KS_PITCH + q4 * 4;
        float* dv = Vs + r * KS_PITCH + q4 * 4;
        dk[0] = kv.x; dk[1] = kv.y; dk[2] = kv.z; dk[3] = kv.w;
        dv[0] = vv.x; dv[1] = vv.y; dv[2] = vv.z; dv[3] = vv.w;
    }
    __syncthreads();

    // ---- phase 1: S[j][k] = scale * dot(Qs[j], Ks[k]) ----
    {
        int kg = t & 31, jg = t >> 5;
        float acc[5][4];
#pragma unroll
        for (int jt = 0; jt < 5; jt++)
#pragma unroll
            for (int kt = 0; kt < 4; kt++) acc[jt][kt] = 0.f;
#pragma unroll 8
        for (int d = 0; d < DD; d++) {
            float qv[5], kv[4];
#pragma unroll
            for (int jt = 0; jt < 5; jt++) qv[jt] = Qs[(jg + 8 * jt) * QS_PITCH + d];
#pragma unroll
            for (int kt = 0; kt < 4; kt++) kv[kt] = Ks[(kg + 32 * kt) * KS_PITCH + d];
#pragma unroll
            for (int jt = 0; jt < 5; jt++)
#pragma unroll
                for (int kt = 0; kt < 4; kt++) acc[jt][kt] += qv[jt] * kv[kt];
        }
#pragma unroll
        for (int jt = 0; jt < 5; jt++)
#pragma unroll
            for (int kt = 0; kt < 4; kt++)
                S[(jg + 8 * jt) * S_PITCH + (kg + 32 * kt)] = acc[jt][kt] * SCALE;
    }
    __syncthreads();

    // ---- phase 2: per-row chunk softmax stats; S <- exp(S - m) ----
    {
        int lane = t & 31, w = t >> 5;
#pragma unroll
        for (int i = 0; i < 5; i++) {
            int j = w * 5 + i;
            float* row = S + j * S_PITCH;
            float v0 = row[lane], v1 = row[lane + 32], v2 = row[lane + 64], v3 = row[lane + 96];
            float m = fmaxf(fmaxf(v0, v1), fmaxf(v2, v3));
            for (int off = 16; off; off >>= 1) m = fmaxf(m, __shfl_xor_sync(0xffffffffu, m, off));
            float e0 = __expf(v0 - m), e1 = __expf(v1 - m);
            float e2 = __expf(v2 - m), e3 = __expf(v3 - m);
            row[lane] = e0; row[lane + 32] = e1; row[lane + 64] = e2; row[lane + 96] = e3;
            float s = e0 + e1 + e2 + e3;
            for (int off = 16; off; off >>= 1) s += __shfl_xor_sync(0xffffffffu, s, off);
            if (lane == 0) {
                g_pm[(bh * UU + j) * NCH + ch] = m;
                g_ps[(bh * UU + j) * NCH + ch] = s;
            }
        }
    }
    __syncthreads();

    // ---- phase 3: partial a[j][d] = sum_k exp * Vs[k][d] (float2 over k) ----
    {
        int d = t & 63, grp = t >> 6;
        float a[10];
#pragma unroll
        for (int jt = 0; jt < 10; jt++) a[jt] = 0.f;
#pragma unroll 2
        for (int k = 0; k < CH; k += 2) {
            float v0 = Vs[k * KS_PITCH + d];
            float v1 = Vs[(k + 1) * KS_PITCH + d];
#pragma unroll
            for (int jt = 0; jt < 10; jt++) {
                float2 sj = *(const float2*)(S + (grp * 10 + jt) * S_PITCH + k);
                a[jt] += sj.x * v0 + sj.y * v1;
            }
        }
#pragma unroll
        for (int jt = 0; jt < 10; jt++)
            g_pa[((bh * UU + grp * 10 + jt) * NCH + ch) * DD + d] = a[jt];
    }
}

// ---------------------------------------------------------------------------
// K6b: merge the 16 chunk partials per (b,h,u); write selected row (over fill).
// ---------------------------------------------------------------------------
__global__ void k_attn_merge(float* __restrict__ out) {
    int u  = blockIdx.x % UU;
    int bh = blockIdx.x / UU;
    int b = bh >> 3, h = bh & 7;
    int d = threadIdx.x;
    int base = (bh * UU + u) * NCH;
    float gm = -CUDART_INF_F;
#pragma unroll
    for (int c = 0; c < NCH; c++) gm = fmaxf(gm, g_pm[base + c]);
    float tot = 0.f, val = 0.f;
#pragma unroll
    for (int c = 0; c < NCH; c++) {
        float e = __expf(g_pm[base + c] - gm);
        tot += g_ps[base + c] * e;
        val += g_pa[(base + c) * DD + d] * e;
    }
    int lq = g_Mtop[bh * UU + u];
    out[(((size_t)(b * LL + lq)) * HH + h) * DD + d] = val / tot;
}

// ---------------------------------------------------------------------------
extern "C" void kernel_launch(void* const* d_in, const int* in_sizes, int n_in,
                              void* d_out, int out_size) {
    const float* Q = (const float*)d_in[0];
    const float* K = (const float*)d_in[1];
    const float* V = (const float*)d_in[2];
    float* out = (float*)d_out;

    cudaFuncSetAttribute(k_attn_part, cudaFuncAttributeMaxDynamicSharedMemorySize,
                         SH_BYTES);
    cudaFuncSetAttribute(k_sampleM2, cudaFuncAttributeMaxDynamicSharedMemorySize,
                         SAMPLE_SH_BYTES);

    k_rng<<<(NEL + 255) / 256, 256>>>();
    k_count<<<LL / 256, 256>>>();
    k_rank<<<NEL / 256, 256>>>();
    k_sampleM2<<<BH * NCHB, 512, SAMPLE_SH_BYTES>>>(Q, K);
    k_topk<<<BH, 512>>>();
    k_vmean<<<BH * 32, 256>>>(V);
    k_fill<<<(BB * LL * HH * (DD / 4)) / 256, 256>>>(out);
    k_attn_part<<<BH * NCH, 256, SH_BYTES>>>(Q, K, V);
    k_attn_merge<<<BH * UU, DD>>>(out);
}

// round 8
// speedup vs baseline: 1.0652x; 1.0652x over previous
#include <cuda_runtime.h>
#include <stdint.h>
#include <math_constants.h>

// ProbSparse attention (Informer) — B=4, L=2048, H=8, D=64, U_part=u=40.
// Layout of all tensors: (B, L, H, D) row-major.

#define BB 4
#define LL 2048
#define HH 8
#define DD 64
#define UU 40
#define SS 40
#define BH (BB*HH)       // 32
#define NEL (LL*SS)      // 81920
#define NCHB 8           // key chunks for sampled-score bucketing
#define CKEY 256         // keys per bucket chunk
#define CSH  8           // log2(CKEY)
#define NCH 16           // key chunks for split-K attention
#define CH  128
#define SCALE 0.125f

__device__ __align__(16) int      g_idx[NEL];
__device__ __align__(16) uint16_t g_cnt16[NCHB*LL];
__device__ __align__(16) uint16_t g_pairs2[NCHB*LL*SS];   // [c][l][<=40]
__device__ __align__(16) float    g_pM[NCHB*BH*LL];
__device__ __align__(16) float    g_pS[NCHB*BH*LL];
__device__ __align__(16) int      g_Mtop[BH*UU];
__device__ __align__(16) float    g_Vmean[BH*DD];
__device__ __align__(16) float    g_pm[BH*UU*NCH];
__device__ __align__(16) float    g_ps[BH*UU*NCH];
__device__ __align__(16) float    g_pa[BH*UU*NCH*DD];

// ---------------------------------------------------------------------------
// Threefry-2x32-20, constexpr-evaluable.
// ---------------------------------------------------------------------------
__host__ __device__ constexpr uint64_t tf2x32(uint32_t k0, uint32_t k1,
                                              uint32_t c0, uint32_t c1) {
    uint32_t ks0 = k0, ks1 = k1, ks2 = k0 ^ k1 ^ 0x1BD11BDAu;
    uint32_t x0 = c0 + ks0, x1 = c1 + ks1;
    const int rotA[4] = {13, 15, 26, 6};
    const int rotB[4] = {17, 29, 16, 24};
    for (int g = 0; g < 5; g++) {
        const int* rot = (g & 1) ? rotB : rotA;
        for (int r = 0; r < 4; r++) {
            x0 += x1;
            x1 = (x1 << rot[r]) | (x1 >> (32 - rot[r]));
            x1 ^= x0;
        }
        uint32_t inj0 = 0, inj1 = 0;
        switch (g) {
            case 0: inj0 = ks1; inj1 = ks2 + 1u; break;
            case 1: inj0 = ks2; inj1 = ks0 + 2u; break;
            case 2: inj0 = ks0; inj1 = ks1 + 3u; break;
            case 3: inj0 = ks1; inj1 = ks2 + 4u; break;
            case 4: inj0 = ks2; inj1 = ks0 + 5u; break;
        }
        x0 += inj0; x1 += inj1;
    }
    return ((uint64_t)x0 << 32) | (uint64_t)x1;
}

constexpr uint64_t K2PAIR = tf2x32(0u, 42u, 0u, 1u);
#define K2_HI ((uint32_t)(K2PAIR >> 32))
#define K2_LO ((uint32_t)(K2PAIR & 0xffffffffu))

// ---------------------------------------------------------------------------
// K1: sampled indices (fold-xor threefry under split key) & 2047.
// Also zeroes g_Vmean.
// ---------------------------------------------------------------------------
__global__ void k_rng() {
    int i = blockIdx.x * blockDim.x + threadIdx.x;
    if (i < BH * DD) g_Vmean[i] = 0.f;
    if (i >= NEL) return;
    uint64_t y = tf2x32(K2_HI, K2_LO, 0u, (uint32_t)i);
    uint32_t bits = (uint32_t)(y >> 32) ^ (uint32_t)(y & 0xffffffffu);
    g_idx[i] = (int)(bits & (LL - 1));
}

// ---------------------------------------------------------------------------
// K1b: per-(chunk,l) counts (8 chunks of 256 keys).
// ---------------------------------------------------------------------------
__global__ void k_count() {
    int l = blockIdx.x * 256 + threadIdx.x;
    if (l >= LL) return;
    int v[SS];
#pragma unroll
    for (int s = 0; s < SS; s++) v[s] = g_idx[l * SS + s] >> CSH;
    int cn[NCHB];
#pragma unroll
    for (int j = 0; j < NCHB; j++) cn[j] = 0;
#pragma unroll
    for (int s = 0; s < SS; s++) {
#pragma unroll
        for (int j = 0; j < NCHB; j++) cn[j] += (v[s] == j);
    }
#pragma unroll
    for (int j = 0; j < NCHB; j++) g_cnt16[j * LL + l] = (uint16_t)cn[j];
}

// ---------------------------------------------------------------------------
// K1c: fully parallel stable scatter into fixed-capacity buckets.
// ---------------------------------------------------------------------------
__global__ void k_rank() {
    int t = blockIdx.x * 256 + threadIdx.x;
    if (t >= NEL) return;
    int l = t / SS, s = t - l * SS;
    int my = g_idx[l * SS + s];
    int c = my >> CSH;
    int rank = 0;
    for (int s2 = 0; s2 < s; s2++)
        rank += ((g_idx[l * SS + s2] >> CSH) == c);
    g_pairs2[(c * LL + l) * SS + rank] = (uint16_t)(my & (CKEY - 1));
}

// ---------------------------------------------------------------------------
// K2: sampled-score partials. Block = (bh, chunk of 256 keys) -> 256 blocks,
// 512 threads, ~72KB smem -> 2 blocks/SM (32 warps/SM). K chunk staged in
// smem (pitch 68 floats, 16B-aligned rows, spread bank starts).
// Half-warp split: lanes 0-15 -> query lA, lanes 16-31 -> lB (2 chains/warp).
// Within a half: 4 slots x 4 lanes; each lane computes a 16-float partial dot
// (4x LDS.128 + 16 FMA), 2 shfl to finish the dot, invalid slots skip LDS.
// ---------------------------------------------------------------------------
#define PIT 68
#define SMP_SH_BYTES (CKEY*PIT*4 + LL*2)

__global__ void __launch_bounds__(512, 2) k_sampleM3(const float* __restrict__ Q,
                                                     const float* __restrict__ K) {
    int c  = blockIdx.x & (NCHB - 1);
    int bh = blockIdx.x >> 3;
    int b = bh >> 3, h = bh & 7;

    extern __shared__ float sk[];                    // [256][68]
    uint16_t* scnt = (uint16_t*)(sk + CKEY * PIT);   // [2048]

    // stage K chunk (256 rows x 256B), coalesced.
    const float* Kc = K + ((size_t)(b * LL + c * CKEY) * HH + h) * DD;
    for (int i = threadIdx.x; i < CKEY * (DD / 4); i += 512) {
        int r = i >> 4, q4 = i & 15;
        float4 v = __ldcg((const float4*)(Kc + (size_t)r * (HH * DD) + q4 * 4));
        *(float4*)(sk + r * PIT + q4 * 4) = v;
    }
    for (int i = threadIdx.x; i < LL; i += 512)
        scnt[i] = g_cnt16[c * LL + i];
    __syncthreads();

    int lane = threadIdx.x & 31, wid = threadIdx.x >> 5;
    int half = lane >> 4;          // 0 -> lA, 1 -> lB
    int hl   = lane & 15;
    int g    = hl >> 2;            // slot 0..3 within half
    int r    = hl & 3;             // d-quarter

    for (int p = wid; p < LL / 2; p += 16) {
        int myl = 2 * p + half;
        int cnt = (int)scnt[myl];
        int mc  = max(cnt, __shfl_xor_sync(0xffffffffu, cnt, 16));

        const float* qrow = Q + ((size_t)(b * LL + myl) * HH + h) * DD + r * 16;
        float4 q0 = __ldcg((const float4*)(qrow));
        float4 q1 = __ldcg((const float4*)(qrow + 4));
        float4 q2 = __ldcg((const float4*)(qrow + 8));
        float4 q3 = __ldcg((const float4*)(qrow + 12));
        const uint16_t* pr = g_pairs2 + (c * LL + myl) * SS;

        float mx = -CUDART_INF_F, sm = 0.f;
        for (int base = 0; base < mc; base += 4) {
            float pv = 0.f;
            bool valid = (base + g) < cnt;
            if (valid) {
                int kl = (int)pr[base + g];
                const float* kr = sk + kl * PIT + r * 16;
                float4 k0 = *(const float4*)(kr);
                float4 k1 = *(const float4*)(kr + 4);
                float4 k2 = *(const float4*)(kr + 8);
                float4 k3 = *(const float4*)(kr + 12);
                float s0 = q0.x * k0.x + q0.y * k0.y + q0.z * k0.z + q0.w * k0.w;
                float s1 = q1.x * k1.x + q1.y * k1.y + q1.z * k1.z + q1.w * k1.w;
                float s2 = q2.x * k2.x + q2.y * k2.y + q2.z * k2.z + q2.w * k2.w;
                float s3 = q3.x * k3.x + q3.y * k3.y + q3.z * k3.z + q3.w * k3.w;
                pv = (s0 + s1) + (s2 + s3);
            }
            pv += __shfl_xor_sync(0xffffffffu, pv, 1);
            pv += __shfl_xor_sync(0xffffffffu, pv, 2);
            if (valid) { mx = fmaxf(mx, pv); sm += pv; }
        }
        // fold the 4 slots within this half (lanes differing in bits 2,3)
        mx = fmaxf(mx, __shfl_xor_sync(0xffffffffu, mx, 4));
        mx = fmaxf(mx, __shfl_xor_sync(0xffffffffu, mx, 8));
        sm += __shfl_xor_sync(0xffffffffu, sm, 4);
        sm += __shfl_xor_sync(0xffffffffu, sm, 8);
        if (hl == 0) {
            g_pM[(c * BH + bh) * LL + myl] = mx;
            g_pS[(c * BH + bh) * LL + myl] = sm;
        }
    }
}

// ---------------------------------------------------------------------------
// K3: merge 8 chunk partials -> M, then exact top-40 per (b,h) via bitonic
// sort of (value,index), comparator (v desc, idx asc). 512 threads.
// ---------------------------------------------------------------------------
__global__ void k_topk() {
    int bh = blockIdx.x;
    __shared__ float sv[LL];
    __shared__ int   si[LL];
    int t = threadIdx.x;
    for (int i = t; i < LL; i += 512) {
        float mm = -CUDART_INF_F, s = 0.f;
#pragma unroll
        for (int c = 0; c < NCHB; c++) {
            mm = fmaxf(mm, g_pM[(c * BH + bh) * LL + i]);
            s += g_pS[(c * BH + bh) * LL + i];
        }
        sv[i] = mm - s * (1.0f / (float)LL);
        si[i] = i;
    }
    __syncthreads();
    for (int k = 2; k <= LL; k <<= 1) {
        for (int j = k >> 1; j > 0; j >>= 1) {
            for (int i = t; i < LL; i += 512) {
                int p = i ^ j;
                if (p > i) {
                    bool asc = (i & k) == 0;
                    float va = sv[i], vp = sv[p];
                    int   ia = si[i], ip = si[p];
                    bool pre = (vp > va) || (vp == va && ip < ia);
                    if (asc == pre) {
                        sv[i] = vp; sv[p] = va;
                        si[i] = ip; si[p] = ia;
                    }
                }
            }
            __syncthreads();
        }
    }
    if (t < UU) g_Mtop[bh * UU + t] = si[t];
}

// ---------------------------------------------------------------------------
// K4: V_mean partials; 1024 blocks (bh x 32 L-chunks of 64), atomicAdd merge.
// ---------------------------------------------------------------------------
__global__ void k_vmean(const float* __restrict__ V) {
    int blk = blockIdx.x;
    int bh = blk >> 5, chn = blk & 31;
    int b = bh >> 3, h = bh & 7;
    int t = threadIdx.x;
    int d = t & 63, sub = t >> 6;
    float s = 0.f;
#pragma unroll 16
    for (int i = 0; i < 16; i++) {
        int l = chn * 64 + sub + i * 4;
        s += V[(((size_t)(b * LL + l)) * HH + h) * DD + d];
    }
    __shared__ float red[256];
    red[t] = s;
    __syncthreads();
    if (t < 64) {
        float tot = red[t] + red[t + 64] + red[t + 128] + red[t + 192];
        atomicAdd(&g_Vmean[bh * DD + t], tot * (1.0f / (float)LL));
    }
}

// ---------------------------------------------------------------------------
// K5: out[b,l,h,:] = V_mean[b,h,:] for all l.
// ---------------------------------------------------------------------------
__global__ void k_fill(float* __restrict__ out) {
    int i = blockIdx.x * blockDim.x + threadIdx.x;
    if (i >= BB * LL * HH * (DD / 4)) return;
    int q4  = i & 15;
    int row = i >> 4;
    int h = row & 7;
    int b = row >> 14;
    float4 vm = reinterpret_cast<const float4*>(g_Vmean)[((b << 3) + h) * (DD / 4) + q4];
    reinterpret_cast<float4*>(out)[i] = vm;
}

// ---------------------------------------------------------------------------
// K6a: split-K attention partials. Block = (b,h, key-chunk of 128), 256 thr.
// ---------------------------------------------------------------------------
#define QS_PITCH 66
#define KS_PITCH 66
#define S_PITCH  130
#define SH_FLOATS (UU*QS_PITCH + CH*KS_PITCH + CH*KS_PITCH + UU*S_PITCH)
#define SH_BYTES  (SH_FLOATS*4 + UU*4)

__global__ void k_attn_part(const float* __restrict__ Q, const float* __restrict__ K,
                            const float* __restrict__ V) {
    int ch = blockIdx.x & (NCH - 1);
    int bh = blockIdx.x >> 4;
    int b = bh >> 3, h = bh & 7;
    int t = threadIdx.x;

    extern __shared__ float sh[];
    float* Qs = sh;                          // [40][66]
    float* Ks = Qs + UU * QS_PITCH;          // [128][66]
    float* Vs = Ks + CH * KS_PITCH;          // [128][66]
    float* S  = Vs + CH * KS_PITCH;          // [40][130]
    int* sidx = (int*)(S + UU * S_PITCH);    // [40]

    if (t < UU) sidx[t] = g_Mtop[bh * UU + t];
    __syncthreads();

    for (int i = t; i < UU * (DD / 4); i += 256) {
        int j = i >> 4, q4 = i & 15;
        float4 v = *(const float4*)(Q + (((size_t)(b * LL + sidx[j])) * HH + h) * DD + q4 * 4);
        float* dst = Qs + j * QS_PITCH + q4 * 4;
        dst[0] = v.x; dst[1] = v.y; dst[2] = v.z; dst[3] = v.w;
    }
    int k0 = ch * CH;
    for (int i = t; i < CH * (DD / 4); i += 256) {
        int r = i >> 4, q4 = i & 15;
        size_t base = (((size_t)(b * LL + k0 + r)) * HH + h) * DD + q4 * 4;
        float4 kv = *(const float4*)(K + base);
        float4 vv = *(const float4*)(V + base);
        float* dk = Ks + r * KS_PITCH + q4 * 4;
        float* dv = Vs + r * KS_PITCH + q4 * 4;
        dk[0] = kv.x; dk[1] = kv.y; dk[2] = kv.z; dk[3] = kv.w;
        dv[0] = vv.x; dv[1] = vv.y; dv[2] = vv.z; dv[3] = vv.w;
    }
    __syncthreads();

    // ---- phase 1: S[j][k] = scale * dot(Qs[j], Ks[k]) ----
    {
        int kg = t & 31, jg = t >> 5;
        float acc[5][4];
#pragma unroll
        for (int jt = 0; jt < 5; jt++)
#pragma unroll
            for (int kt = 0; kt < 4; kt++) acc[jt][kt] = 0.f;
#pragma unroll 8
        for (int d = 0; d < DD; d++) {
            float qv[5], kv[4];
#pragma unroll
            for (int jt = 0; jt < 5; jt++) qv[jt] = Qs[(jg + 8 * jt) * QS_PITCH + d];
#pragma unroll
            for (int kt = 0; kt < 4; kt++) kv[kt] = Ks[(kg + 32 * kt) * KS_PITCH + d];
#pragma unroll
            for (int jt = 0; jt < 5; jt++)
#pragma unroll
                for (int kt = 0; kt < 4; kt++) acc[jt][kt] += qv[jt] * kv[kt];
        }
#pragma unroll
        for (int jt = 0; jt < 5; jt++)
#pragma unroll
            for (int kt = 0; kt < 4; kt++)
                S[(jg + 8 * jt) * S_PITCH + (kg + 32 * kt)] = acc[jt][kt] * SCALE;
    }
    __syncthreads();

    // ---- phase 2: per-row chunk softmax stats; S <- exp(S - m) ----
    {
        int lane = t & 31, w = t >> 5;
#pragma unroll
        for (int i = 0; i < 5; i++) {
            int j = w * 5 + i;
            float* row = S + j * S_PITCH;
            float v0 = row[lane], v1 = row[lane + 32], v2 = row[lane + 64], v3 = row[lane + 96];
            float m = fmaxf(fmaxf(v0, v1), fmaxf(v2, v3));
            for (int off = 16; off; off >>= 1) m = fmaxf(m, __shfl_xor_sync(0xffffffffu, m, off));
            float e0 = __expf(v0 - m), e1 = __expf(v1 - m);
            float e2 = __expf(v2 - m), e3 = __expf(v3 - m);
            row[lane] = e0; row[lane + 32] = e1; row[lane + 64] = e2; row[lane + 96] = e3;
            float s = e0 + e1 + e2 + e3;
            for (int off = 16; off; off >>= 1) s += __shfl_xor_sync(0xffffffffu, s, off);
            if (lane == 0) {
                g_pm[(bh * UU + j) * NCH + ch] = m;
                g_ps[(bh * UU + j) * NCH + ch] = s;
            }
        }
    }
    __syncthreads();

    // ---- phase 3: partial a[j][d] = sum_k exp * Vs[k][d] (float2 over k) ----
    {
        int d = t & 63, grp = t >> 6;
        float a[10];
#pragma unroll
        for (int jt = 0; jt < 10; jt++) a[jt] = 0.f;
#pragma unroll 2
        for (int k = 0; k < CH; k += 2) {
            float v0 = Vs[k * KS_PITCH + d];
            float v1 = Vs[(k + 1) * KS_PITCH + d];
#pragma unroll
            for (int jt = 0; jt < 10; jt++) {
                float2 sj = *(const float2*)(S + (grp * 10 + jt) * S_PITCH + k);
                a[jt] += sj.x * v0 + sj.y * v1;
            }
        }
#pragma unroll
        for (int jt = 0; jt < 10; jt++)
            g_pa[((bh * UU + grp * 10 + jt) * NCH + ch) * DD + d] = a[jt];
    }
}

// ---------------------------------------------------------------------------
// K6b: merge the 16 chunk partials per (b,h,u); write selected row (over fill).
// ---------------------------------------------------------------------------
__global__ void k_attn_merge(float* __restrict__ out) {
    int u  = blockIdx.x % UU;
    int bh = blockIdx.x / UU;
    int b = bh >> 3, h = bh & 7;
    int d = threadIdx.x;
    int base = (bh * UU + u) * NCH;
    float gm = -CUDART_INF_F;
#pragma unroll
    for (int c = 0; c < NCH; c++) gm = fmaxf(gm, g_pm[base + c]);
    float tot = 0.f, val = 0.f;
#pragma unroll
    for (int c = 0; c < NCH; c++) {
        float e = __expf(g_pm[base + c] - gm);
        tot += g_ps[base + c] * e;
        val += g_pa[(base + c) * DD + d] * e;
    }
    int lq = g_Mtop[bh * UU + u];
    out[(((size_t)(b * LL + lq)) * HH + h) * DD + d] = val / tot;
}

// ---------------------------------------------------------------------------
extern "C" void kernel_launch(void* const* d_in, const int* in_sizes, int n_in,
                              void* d_out, int out_size) {
    const float* Q = (const float*)d_in[0];
    const float* K = (const float*)d_in[1];
    const float* V = (const float*)d_in[2];
    float* out = (float*)d_out;

    cudaFuncSetAttribute(k_attn_part, cudaFuncAttributeMaxDynamicSharedMemorySize,
                         SH_BYTES);
    cudaFuncSetAttribute(k_sampleM3, cudaFuncAttributeMaxDynamicSharedMemorySize,
                         SMP_SH_BYTES);

    k_rng<<<(NEL + 255) / 256, 256>>>();
    k_count<<<LL / 256, 256>>>();
    k_rank<<<NEL / 256, 256>>>();
    k_sampleM3<<<BH * NCHB, 512, SMP_SH_BYTES>>>(Q, K);
    k_topk<<<BH, 512>>>();
    k_vmean<<<BH * 32, 256>>>(V);
    k_fill<<<(BB * LL * HH * (DD / 4)) / 256, 256>>>(out);
    k_attn_part<<<BH * NCH, 256, SH_BYTES>>>(Q, K, V);
    k_attn_merge<<<BH * UU, DD>>>(out);
}

// round 9
// speedup vs baseline: 1.1811x; 1.1088x over previous
#include <cuda_runtime.h>
#include <stdint.h>
#include <math_constants.h>

// ProbSparse attention (Informer) — B=4, L=2048, H=8, D=64, U_part=u=40.
// Layout of all tensors: (B, L, H, D) row-major.

#define BB 4
#define LL 2048
#define HH 8
#define DD 64
#define UU 40
#define SS 40
#define BH (BB*HH)       // 32
#define NEL (LL*SS)      // 81920
#define NCHB 8           // key chunks for sampled-score bucketing
#define CKEY 256         // keys per bucket chunk
#define CSH  8           // log2(CKEY)
#define NCH 16           // key chunks for split-K attention
#define CH  128
#define SCALE 0.125f

__device__ __align__(16) int      g_idx[NEL];
__device__ __align__(16) uint16_t g_cnt16[NCHB*LL];
__device__ __align__(16) uint16_t g_pairs2[NCHB*LL*SS];   // [c][l][<=40]
__device__ __align__(16) float    g_pM[NCHB*BH*LL];
__device__ __align__(16) float    g_pS[NCHB*BH*LL];
__device__ __align__(16) int      g_Mtop[BH*UU];
__device__ __align__(16) float    g_Vmean[BH*DD];
__device__ __align__(16) float    g_pm[BH*UU*NCH];
__device__ __align__(16) float    g_ps[BH*UU*NCH];
__device__ __align__(16) float    g_pa[BH*UU*NCH*DD];

// ---------------------------------------------------------------------------
// Threefry-2x32-20, constexpr-evaluable.
// ---------------------------------------------------------------------------
__host__ __device__ constexpr uint64_t tf2x32(uint32_t k0, uint32_t k1,
                                              uint32_t c0, uint32_t c1) {
    uint32_t ks0 = k0, ks1 = k1, ks2 = k0 ^ k1 ^ 0x1BD11BDAu;
    uint32_t x0 = c0 + ks0, x1 = c1 + ks1;
    const int rotA[4] = {13, 15, 26, 6};
    const int rotB[4] = {17, 29, 16, 24};
    for (int g = 0; g < 5; g++) {
        const int* rot = (g & 1) ? rotB : rotA;
        for (int r = 0; r < 4; r++) {
            x0 += x1;
            x1 = (x1 << rot[r]) | (x1 >> (32 - rot[r]));
            x1 ^= x0;
        }
        uint32_t inj0 = 0, inj1 = 0;
        switch (g) {
            case 0: inj0 = ks1; inj1 = ks2 + 1u; break;
            case 1: inj0 = ks2; inj1 = ks0 + 2u; break;
            case 2: inj0 = ks0; inj1 = ks1 + 3u; break;
            case 3: inj0 = ks1; inj1 = ks2 + 4u; break;
            case 4: inj0 = ks2; inj1 = ks0 + 5u; break;
        }
        x0 += inj0; x1 += inj1;
    }
    return ((uint64_t)x0 << 32) | (uint64_t)x1;
}

constexpr uint64_t K2PAIR = tf2x32(0u, 42u, 0u, 1u);
#define K2_HI ((uint32_t)(K2PAIR >> 32))
#define K2_LO ((uint32_t)(K2PAIR & 0xffffffffu))

// ---------------------------------------------------------------------------
// K1: sampled indices (fold-xor threefry under split key) & 2047.
// Also zeroes g_Vmean.
// ---------------------------------------------------------------------------
__global__ void k_rng() {
    int i = blockIdx.x * blockDim.x + threadIdx.x;
    if (i < BH * DD) g_Vmean[i] = 0.f;
    if (i >= NEL) return;
    uint64_t y = tf2x32(K2_HI, K2_LO, 0u, (uint32_t)i);
    uint32_t bits = (uint32_t)(y >> 32) ^ (uint32_t)(y & 0xffffffffu);
    g_idx[i] = (int)(bits & (LL - 1));
}

// ---------------------------------------------------------------------------
// K1b: per-(chunk,l) counts (8 chunks of 256 keys).
// ---------------------------------------------------------------------------
__global__ void k_count() {
    int l = blockIdx.x * 256 + threadIdx.x;
    if (l >= LL) return;
    int v[SS];
#pragma unroll
    for (int s = 0; s < SS; s++) v[s] = g_idx[l * SS + s] >> CSH;
    int cn[NCHB];
#pragma unroll
    for (int j = 0; j < NCHB; j++) cn[j] = 0;
#pragma unroll
    for (int s = 0; s < SS; s++) {
#pragma unroll
        for (int j = 0; j < NCHB; j++) cn[j] += (v[s] == j);
    }
#pragma unroll
    for (int j = 0; j < NCHB; j++) g_cnt16[j * LL + l] = (uint16_t)cn[j];
}

// ---------------------------------------------------------------------------
// K1c: fully parallel stable scatter into fixed-capacity buckets.
// ---------------------------------------------------------------------------
__global__ void k_rank() {
    int t = blockIdx.x * 256 + threadIdx.x;
    if (t >= NEL) return;
    int l = t / SS, s = t - l * SS;
    int my = g_idx[l * SS + s];
    int c = my >> CSH;
    int rank = 0;
    for (int s2 = 0; s2 < s; s2++)
        rank += ((g_idx[l * SS + s2] >> CSH) == c);
    g_pairs2[(c * LL + l) * SS + rank] = (uint16_t)(my & (CKEY - 1));
}

// ---------------------------------------------------------------------------
// K2: sampled-score partials. Block = (bh, chunk of 256 keys) -> 256 blocks,
// 512 threads, 68KB smem. K chunk staged in smem, pitch 64 (no padding —
// every LDS.128 phase below reads one contiguous 128B row segment).
// Octet scheme: 8 lanes per sample; lane oj reads float4 at row+oj*4 and
// row+32+oj*4 -> each quarter-warp phase = one octet = contiguous 128B =
// 32 distinct banks, CONFLICT-FREE. 4 samples/warp-iter, 3 shfl to reduce
// each octet dot, then fold across octets (xor 8, 16).
// ---------------------------------------------------------------------------
#define SMP_SH_BYTES (CKEY*DD*4 + LL*2)

__global__ void __launch_bounds__(512, 2) k_sampleM3(const float* __restrict__ Q,
                                                     const float* __restrict__ K) {
    int c  = blockIdx.x & (NCHB - 1);
    int bh = blockIdx.x >> 3;
    int b = bh >> 3, h = bh & 7;

    extern __shared__ float sk[];                    // [256][64]
    uint16_t* scnt = (uint16_t*)(sk + CKEY * DD);    // [2048]

    // stage K chunk (256 rows x 256B), coalesced.
    const float* Kc = K + ((size_t)(b * LL + c * CKEY) * HH + h) * DD;
    for (int i = threadIdx.x; i < CKEY * (DD / 4); i += 512) {
        int r = i >> 4, q4 = i & 15;
        float4 v = __ldcg((const float4*)(Kc + (size_t)r * (HH * DD) + q4 * 4));
        *(float4*)(sk + r * DD + q4 * 4) = v;
    }
    for (int i = threadIdx.x; i < LL; i += 512)
        scnt[i] = g_cnt16[c * LL + i];
    __syncthreads();

    int lane = threadIdx.x & 31, wid = threadIdx.x >> 5;
    int oct = lane >> 3;           // sample slot 0..3
    int oj  = lane & 7;            // position within octet

    for (int l = wid; l < LL; l += 16) {
        int cnt = (int)scnt[l];
        const float* qrow = Q + ((size_t)(b * LL + l) * HH + h) * DD;
        float4 qa = __ldcg((const float4*)(qrow + oj * 4));
        float4 qb = __ldcg((const float4*)(qrow + 32 + oj * 4));
        const uint16_t* pr = g_pairs2 + (c * LL + l) * SS;

        float mx = -CUDART_INF_F, sm = 0.f;
        for (int t0 = 0; t0 < cnt; t0 += 4) {
            int myt = t0 + oct;
            bool valid = myt < cnt;
            int kloc = valid ? (int)pr[myt] : 0;
            const float* krow = sk + kloc * DD;
            float4 ka = *(const float4*)(krow + oj * 4);
            float4 kb = *(const float4*)(krow + 32 + oj * 4);
            float p = qa.x * ka.x + qa.y * ka.y + qa.z * ka.z + qa.w * ka.w
                    + qb.x * kb.x + qb.y * kb.y + qb.z * kb.z + qb.w * kb.w;
            p += __shfl_xor_sync(0xffffffffu, p, 1);
            p += __shfl_xor_sync(0xffffffffu, p, 2);
            p += __shfl_xor_sync(0xffffffffu, p, 4);
            if (valid) { mx = fmaxf(mx, p); sm += p; }
        }
        // fold the 4 octet slot-accumulators (fixed order -> deterministic)
        mx = fmaxf(mx, __shfl_xor_sync(0xffffffffu, mx, 8));
        mx = fmaxf(mx, __shfl_xor_sync(0xffffffffu, mx, 16));
        sm += __shfl_xor_sync(0xffffffffu, sm, 8);
        sm += __shfl_xor_sync(0xffffffffu, sm, 16);
        if (lane == 0) {
            g_pM[(c * BH + bh) * LL + l] = mx;
            g_pS[(c * BH + bh) * LL + l] = sm;
        }
    }
}

// ---------------------------------------------------------------------------
// K3: merge 8 chunk partials -> M, then exact top-40 per (b,h) via bitonic
// sort of (value,index), comparator (v desc, idx asc). 512 threads.
// ---------------------------------------------------------------------------
__global__ void k_topk() {
    int bh = blockIdx.x;
    __shared__ float sv[LL];
    __shared__ int   si[LL];
    int t = threadIdx.x;
    for (int i = t; i < LL; i += 512) {
        float mm = -CUDART_INF_F, s = 0.f;
#pragma unroll
        for (int c = 0; c < NCHB; c++) {
            mm = fmaxf(mm, g_pM[(c * BH + bh) * LL + i]);
            s += g_pS[(c * BH + bh) * LL + i];
        }
        sv[i] = mm - s * (1.0f / (float)LL);
        si[i] = i;
    }
    __syncthreads();
    for (int k = 2; k <= LL; k <<= 1) {
        for (int j = k >> 1; j > 0; j >>= 1) {
            for (int i = t; i < LL; i += 512) {
                int p = i ^ j;
                if (p > i) {
                    bool asc = (i & k) == 0;
                    float va = sv[i], vp = sv[p];
                    int   ia = si[i], ip = si[p];
                    bool pre = (vp > va) || (vp == va && ip < ia);
                    if (asc == pre) {
                        sv[i] = vp; sv[p] = va;
                        si[i] = ip; si[p] = ia;
                    }
                }
            }
            __syncthreads();
        }
    }
    if (t < UU) g_Mtop[bh * UU + t] = si[t];
}

// ---------------------------------------------------------------------------
// K4: V_mean partials; 1024 blocks (bh x 32 L-chunks of 64), atomicAdd merge.
// ---------------------------------------------------------------------------
__global__ void k_vmean(const float* __restrict__ V) {
    int blk = blockIdx.x;
    int bh = blk >> 5, chn = blk & 31;
    int b = bh >> 3, h = bh & 7;
    int t = threadIdx.x;
    int d = t & 63, sub = t >> 6;
    float s = 0.f;
#pragma unroll 16
    for (int i = 0; i < 16; i++) {
        int l = chn * 64 + sub + i * 4;
        s += V[(((size_t)(b * LL + l)) * HH + h) * DD + d];
    }
    __shared__ float red[256];
    red[t] = s;
    __syncthreads();
    if (t < 64) {
        float tot = red[t] + red[t + 64] + red[t + 128] + red[t + 192];
        atomicAdd(&g_Vmean[bh * DD + t], tot * (1.0f / (float)LL));
    }
}

// ---------------------------------------------------------------------------
// K5: out[b,l,h,:] = V_mean[b,h,:] for all l.
// ---------------------------------------------------------------------------
__global__ void k_fill(float* __restrict__ out) {
    int i = blockIdx.x * blockDim.x + threadIdx.x;
    if (i >= BB * LL * HH * (DD / 4)) return;
    int q4  = i & 15;
    int row = i >> 4;
    int h = row & 7;
    int b = row >> 14;
    float4 vm = reinterpret_cast<const float4*>(g_Vmean)[((b << 3) + h) * (DD / 4) + q4];
    reinterpret_cast<float4*>(out)[i] = vm;
}

// ---------------------------------------------------------------------------
// K6a: split-K attention partials. Block = (b,h, key-chunk of 128), 256 thr.
// ---------------------------------------------------------------------------
#define QS_PITCH 66
#define KS_PITCH 66
#define S_PITCH  130
#define SH_FLOATS (UU*QS_PITCH + CH*KS_PITCH + CH*KS_PITCH + UU*S_PITCH)
#define SH_BYTES  (SH_FLOATS*4 + UU*4)

__global__ void k_attn_part(const float* __restrict__ Q, const float* __restrict__ K,
                            const float* __restrict__ V) {
    int ch = blockIdx.x & (NCH - 1);
    int bh = blockIdx.x >> 4;
    int b = bh >> 3, h = bh & 7;
    int t = threadIdx.x;

    extern __shared__ float sh[];
    float* Qs = sh;                          // [40][66]
    float* Ks = Qs + UU * QS_PITCH;          // [128][66]
    float* Vs = Ks + CH * KS_PITCH;          // [128][66]
    float* S  = Vs + CH * KS_PITCH;          // [40][130]
    int* sidx = (int*)(S + UU * S_PITCH);    // [40]

    if (t < UU) sidx[t] = g_Mtop[bh * UU + t];
    __syncthreads();

    for (int i = t; i < UU * (DD / 4); i += 256) {
        int j = i >> 4, q4 = i & 15;
        float4 v = *(const float4*)(Q + (((size_t)(b * LL + sidx[j])) * HH + h) * DD + q4 * 4);
        float* dst = Qs + j * QS_PITCH + q4 * 4;
        dst[0] = v.x; dst[1] = v.y; dst[2] = v.z; dst[3] = v.w;
    }
    int k0 = ch * CH;
    for (int i = t; i < CH * (DD / 4); i += 256) {
        int r = i >> 4, q4 = i & 15;
        size_t base = (((size_t)(b * LL + k0 + r)) * HH + h) * DD + q4 * 4;
        float4 kv = *(const float4*)(K + base);
        float4 vv = *(const float4*)(V + base);
        float* dk = Ks + r * KS_PITCH + q4 * 4;
        float* dv = Vs + r * KS_PITCH + q4 * 4;
        dk[0] = kv.x; dk[1] = kv.y; dk[2] = kv.z; dk[3] = kv.w;
        dv[0] = vv.x; dv[1] = vv.y; dv[2] = vv.z; dv[3] = vv.w;
    }
    __syncthreads();

    // ---- phase 1: S[j][k] = scale * dot(Qs[j], Ks[k]) ----
    {
        int kg = t & 31, jg = t >> 5;
        float acc[5][4];
#pragma unroll
        for (int jt = 0; jt < 5; jt++)
#pragma unroll
            for (int kt = 0; kt < 4; kt++) acc[jt][kt] = 0.f;
#pragma unroll 8
        for (int d = 0; d < DD; d++) {
            float qv[5], kv[4];
#pragma unroll
            for (int jt = 0; jt < 5; jt++) qv[jt] = Qs[(jg + 8 * jt) * QS_PITCH + d];
#pragma unroll
            for (int kt = 0; kt < 4; kt++) kv[kt] = Ks[(kg + 32 * kt) * KS_PITCH + d];
#pragma unroll
            for (int jt = 0; jt < 5; jt++)
#pragma unroll
                for (int kt = 0; kt < 4; kt++) acc[jt][kt] += qv[jt] * kv[kt];
        }
#pragma unroll
        for (int jt = 0; jt < 5; jt++)
#pragma unroll
            for (int kt = 0; kt < 4; kt++)
                S[(jg + 8 * jt) * S_PITCH + (kg + 32 * kt)] = acc[jt][kt] * SCALE;
    }
    __syncthreads();

    // ---- phase 2: per-row chunk softmax stats; S <- exp(S - m) ----
    {
        int lane = t & 31, w = t >> 5;
#pragma unroll
        for (int i = 0; i < 5; i++) {
            int j = w * 5 + i;
            float* row = S + j * S_PITCH;
            float v0 = row[lane], v1 = row[lane + 32], v2 = row[lane + 64], v3 = row[lane + 96];
            float m = fmaxf(fmaxf(v0, v1), fmaxf(v2, v3));
            for (int off = 16; off; off >>= 1) m = fmaxf(m, __shfl_xor_sync(0xffffffffu, m, off));
            float e0 = __expf(v0 - m), e1 = __expf(v1 - m);
            float e2 = __expf(v2 - m), e3 = __expf(v3 - m);
            row[lane] = e0; row[lane + 32] = e1; row[lane + 64] = e2; row[lane + 96] = e3;
            float s = e0 + e1 + e2 + e3;
            for (int off = 16; off; off >>= 1) s += __shfl_xor_sync(0xffffffffu, s, off);
            if (lane == 0) {
                g_pm[(bh * UU + j) * NCH + ch] = m;
                g_ps[(bh * UU + j) * NCH + ch] = s;
            }
        }
    }
    __syncthreads();

    // ---- phase 3: partial a[j][d] = sum_k exp * Vs[k][d] (float2 over k) ----
    {
        int d = t & 63, grp = t >> 6;
        float a[10];
#pragma unroll
        for (int jt = 0; jt < 10; jt++) a[jt] = 0.f;
#pragma unroll 2
        for (int k = 0; k < CH; k += 2) {
            float v0 = Vs[k * KS_PITCH + d];
            float v1 = Vs[(k + 1) * KS_PITCH + d];
#pragma unroll
            for (int jt = 0; jt < 10; jt++) {
                float2 sj = *(const float2*)(S + (grp * 10 + jt) * S_PITCH + k);
                a[jt] += sj.x * v0 + sj.y * v1;
            }
        }
#pragma unroll
        for (int jt = 0; jt < 10; jt++)
            g_pa[((bh * UU + grp * 10 + jt) * NCH + ch) * DD + d] = a[jt];
    }
}

// ---------------------------------------------------------------------------
// K6b: merge the 16 chunk partials per (b,h,u); write selected row (over fill).
// ---------------------------------------------------------------------------
__global__ void k_attn_merge(float* __restrict__ out) {
    int u  = blockIdx.x % UU;
    int bh = blockIdx.x / UU;
    int b = bh >> 3, h = bh & 7;
    int d = threadIdx.x;
    int base = (bh * UU + u) * NCH;
    float gm = -CUDART_INF_F;
#pragma unroll
    for (int c = 0; c < NCH; c++) gm = fmaxf(gm, g_pm[base + c]);
    float tot = 0.f, val = 0.f;
#pragma unroll
    for (int c = 0; c < NCH; c++) {
        float e = __expf(g_pm[base + c] - gm);
        tot += g_ps[base + c] * e;
        val += g_pa[(base + c) * DD + d] * e;
    }
    int lq = g_Mtop[bh * UU + u];
    out[(((size_t)(b * LL + lq)) * HH + h) * DD + d] = val / tot;
}

// ---------------------------------------------------------------------------
extern "C" void kernel_launch(void* const* d_in, const int* in_sizes, int n_in,
                              void* d_out, int out_size) {
    const float* Q = (const float*)d_in[0];
    const float* K = (const float*)d_in[1];
    const float* V = (const float*)d_in[2];
    float* out = (float*)d_out;

    cudaFuncSetAttribute(k_attn_part, cudaFuncAttributeMaxDynamicSharedMemorySize,
                         SH_BYTES);
    cudaFuncSetAttribute(k_sampleM3, cudaFuncAttributeMaxDynamicSharedMemorySize,
                         SMP_SH_BYTES);

    k_rng<<<(NEL + 255) / 256, 256>>>();
    k_count<<<LL / 256, 256>>>();
    k_rank<<<NEL / 256, 256>>>();
    k_sampleM3<<<BH * NCHB, 512, SMP_SH_BYTES>>>(Q, K);
    k_topk<<<BH, 512>>>();
    k_vmean<<<BH * 32, 256>>>(V);
    k_fill<<<(BB * LL * HH * (DD / 4)) / 256, 256>>>(out);
    k_attn_part<<<BH * NCH, 256, SH_BYTES>>>(Q, K, V);
    k_attn_merge<<<BH * UU, DD>>>(out);
}

// round 10
// speedup vs baseline: 1.4024x; 1.1874x over previous
#include <cuda_runtime.h>
#include <stdint.h>
#include <math_constants.h>

// ProbSparse attention (Informer) — B=4, L=2048, H=8, D=64, U_part=u=40.
// Layout of all tensors: (B, L, H, D) row-major.

#define BB 4
#define LL 2048
#define HH 8
#define DD 64
#define UU 40
#define SS 40
#define BH (BB*HH)       // 32
#define NEL (LL*SS)      // 81920
#define NCHB 4           // key chunks for sampled-score bucketing
#define CKEY 512         // keys per bucket chunk
#define CSH  9           // log2(CKEY)
#define NCH 16           // key chunks for split-K attention
#define CH  128
#define SCALE 0.125f

__device__ __align__(16) int      g_idx[NEL];
__device__ __align__(16) uint16_t g_cnt16[NCHB*LL];
__device__ __align__(16) uint16_t g_pairs2[NCHB*LL*SS];   // [c][l][<=40]
__device__ __align__(16) float    g_pM[NCHB*BH*LL];
__device__ __align__(16) float    g_pS[NCHB*BH*LL];
__device__ __align__(16) int      g_Mtop[BH*UU];
__device__ __align__(16) float    g_Vmean[BH*DD];
__device__ __align__(16) float    g_pm[BH*UU*NCH];
__device__ __align__(16) float    g_ps[BH*UU*NCH];
__device__ __align__(16) float    g_pa[BH*UU*NCH*DD];

// ---------------------------------------------------------------------------
// Threefry-2x32-20, constexpr-evaluable.
// ---------------------------------------------------------------------------
__host__ __device__ constexpr uint64_t tf2x32(uint32_t k0, uint32_t k1,
                                              uint32_t c0, uint32_t c1) {
    uint32_t ks0 = k0, ks1 = k1, ks2 = k0 ^ k1 ^ 0x1BD11BDAu;
    uint32_t x0 = c0 + ks0, x1 = c1 + ks1;
    const int rotA[4] = {13, 15, 26, 6};
    const int rotB[4] = {17, 29, 16, 24};
    for (int g = 0; g < 5; g++) {
        const int* rot = (g & 1) ? rotB : rotA;
        for (int r = 0; r < 4; r++) {
            x0 += x1;
            x1 = (x1 << rot[r]) | (x1 >> (32 - rot[r]));
            x1 ^= x0;
        }
        uint32_t inj0 = 0, inj1 = 0;
        switch (g) {
            case 0: inj0 = ks1; inj1 = ks2 + 1u; break;
            case 1: inj0 = ks2; inj1 = ks0 + 2u; break;
            case 2: inj0 = ks0; inj1 = ks1 + 3u; break;
            case 3: inj0 = ks1; inj1 = ks2 + 4u; break;
            case 4: inj0 = ks2; inj1 = ks0 + 5u; break;
        }
        x0 += inj0; x1 += inj1;
    }
    return ((uint64_t)x0 << 32) | (uint64_t)x1;
}

constexpr uint64_t K2PAIR = tf2x32(0u, 42u, 0u, 1u);
#define K2_HI ((uint32_t)(K2PAIR >> 32))
#define K2_LO ((uint32_t)(K2PAIR & 0xffffffffu))

// ---------------------------------------------------------------------------
// K1: sampled indices (fold-xor threefry under split key) & 2047.
// Also zeroes g_Vmean.
// ---------------------------------------------------------------------------
__global__ void k_rng() {
    int i = blockIdx.x * blockDim.x + threadIdx.x;
    if (i < BH * DD) g_Vmean[i] = 0.f;
    if (i >= NEL) return;
    uint64_t y = tf2x32(K2_HI, K2_LO, 0u, (uint32_t)i);
    uint32_t bits = (uint32_t)(y >> 32) ^ (uint32_t)(y & 0xffffffffu);
    g_idx[i] = (int)(bits & (LL - 1));
}

// ---------------------------------------------------------------------------
// K1b: per-(chunk,l) counts (4 chunks of 512 keys).
// ---------------------------------------------------------------------------
__global__ void k_count() {
    int l = blockIdx.x * 256 + threadIdx.x;
    if (l >= LL) return;
    int v[SS];
#pragma unroll
    for (int s = 0; s < SS; s++) v[s] = g_idx[l * SS + s] >> CSH;
    int cn[NCHB];
#pragma unroll
    for (int j = 0; j < NCHB; j++) cn[j] = 0;
#pragma unroll
    for (int s = 0; s < SS; s++) {
#pragma unroll
        for (int j = 0; j < NCHB; j++) cn[j] += (v[s] == j);
    }
#pragma unroll
    for (int j = 0; j < NCHB; j++) g_cnt16[j * LL + l] = (uint16_t)cn[j];
}

// ---------------------------------------------------------------------------
// K1c: fully parallel stable scatter into fixed-capacity buckets.
// ---------------------------------------------------------------------------
__global__ void k_rank() {
    int t = blockIdx.x * 256 + threadIdx.x;
    if (t >= NEL) return;
    int l = t / SS, s = t - l * SS;
    int my = g_idx[l * SS + s];
    int c = my >> CSH;
    int rank = 0;
    for (int s2 = 0; s2 < s; s2++)
        rank += ((g_idx[l * SS + s2] >> CSH) == c);
    g_pairs2[(c * LL + l) * SS + rank] = (uint16_t)(my & (CKEY - 1));
}

// ---------------------------------------------------------------------------
// K2: sampled-score partials. Block = (bh, chunk of 512 keys) -> 128 blocks,
// 1024 threads (32 warps), 132KB smem -> 1 block/SM but 8 warps/SMSP.
// K chunk staged in smem at pitch 64: every LDS.128 quarter-warp phase is one
// octet reading one contiguous 128B row segment -> conflict-free.
// Pair lists preloaded per l into lane registers (1 coalesced LDG.U16), inner
// loop distributes kloc via one shfl. 4 samples/warp-iter, octet dots.
// ---------------------------------------------------------------------------
#define SMP_SH_BYTES (CKEY*DD*4 + LL*2)

__global__ void __launch_bounds__(1024, 1) k_sampleM4(const float* __restrict__ Q,
                                                      const float* __restrict__ K) {
    int c  = blockIdx.x & (NCHB - 1);
    int bh = blockIdx.x >> 2;
    int b = bh >> 3, h = bh & 7;

    extern __shared__ float sk[];                    // [512][64]
    uint16_t* scnt = (uint16_t*)(sk + CKEY * DD);    // [2048]

    // stage K chunk (512 rows x 256B), coalesced.
    const float* Kc = K + ((size_t)(b * LL + c * CKEY) * HH + h) * DD;
    for (int i = threadIdx.x; i < CKEY * (DD / 4); i += 1024) {
        int r = i >> 4, q4 = i & 15;
        float4 v = __ldcg((const float4*)(Kc + (size_t)r * (HH * DD) + q4 * 4));
        *(float4*)(sk + r * DD + q4 * 4) = v;
    }
    for (int i = threadIdx.x; i < LL; i += 1024)
        scnt[i] = g_cnt16[c * LL + i];
    __syncthreads();

    int lane = threadIdx.x & 31, wid = threadIdx.x >> 5;
    int oct = lane >> 3;           // sample slot 0..3
    int oj  = lane & 7;            // position within octet

    for (int l = wid; l < LL; l += 32) {
        int cnt = (int)scnt[l];
        const float* qrow = Q + ((size_t)(b * LL + l) * HH + h) * DD;
        float4 qa = __ldcg((const float4*)(qrow + oj * 4));
        float4 qb = __ldcg((const float4*)(qrow + 32 + oj * 4));
        const uint16_t* pr = g_pairs2 + (c * LL + l) * SS;
        int pa = (lane < cnt) ? (int)pr[lane] : 0;
        int pb = (lane + 32 < cnt) ? (int)pr[lane + 32] : 0;

        float mx = -CUDART_INF_F, sm = 0.f;
        for (int t0 = 0; t0 < cnt; t0 += 4) {
            int src = t0 + oct;                 // sample index for this slot
            int kloc = (t0 < 32)
                     ? __shfl_sync(0xffffffffu, pa, src & 31)
                     : __shfl_sync(0xffffffffu, pb, src - 32);
            bool valid = src < cnt;
            const float* krow = sk + kloc * DD;
            float4 ka = *(const float4*)(krow + oj * 4);
            float4 kb = *(const float4*)(krow + 32 + oj * 4);
            float p = qa.x * ka.x + qa.y * ka.y + qa.z * ka.z + qa.w * ka.w
                    + qb.x * kb.x + qb.y * kb.y + qb.z * kb.z + qb.w * kb.w;
            p += __shfl_xor_sync(0xffffffffu, p, 1);
            p += __shfl_xor_sync(0xffffffffu, p, 2);
            p += __shfl_xor_sync(0xffffffffu, p, 4);
            if (valid) { mx = fmaxf(mx, p); sm += p; }
        }
        // fold the 4 octet slot-accumulators (fixed order -> deterministic)
        mx = fmaxf(mx, __shfl_xor_sync(0xffffffffu, mx, 8));
        mx = fmaxf(mx, __shfl_xor_sync(0xffffffffu, mx, 16));
        sm += __shfl_xor_sync(0xffffffffu, sm, 8);
        sm += __shfl_xor_sync(0xffffffffu, sm, 16);
        if (lane == 0) {
            g_pM[(c * BH + bh) * LL + l] = mx;
            g_pS[(c * BH + bh) * LL + l] = sm;
        }
    }
}

// ---------------------------------------------------------------------------
// K3: merge 4 chunk partials -> M, then exact top-40 per (b,h) via bitonic
// sort of (value,index), comparator (v desc, idx asc). 512 threads.
// ---------------------------------------------------------------------------
__global__ void k_topk() {
    int bh = blockIdx.x;
    __shared__ float sv[LL];
    __shared__ int   si[LL];
    int t = threadIdx.x;
    for (int i = t; i < LL; i += 512) {
        float mm = -CUDART_INF_F, s = 0.f;
#pragma unroll
        for (int c = 0; c < NCHB; c++) {
            mm = fmaxf(mm, g_pM[(c * BH + bh) * LL + i]);
            s += g_pS[(c * BH + bh) * LL + i];
        }
        sv[i] = mm - s * (1.0f / (float)LL);
        si[i] = i;
    }
    __syncthreads();
    for (int k = 2; k <= LL; k <<= 1) {
        for (int j = k >> 1; j > 0; j >>= 1) {
            for (int i = t; i < LL; i += 512) {
                int p = i ^ j;
                if (p > i) {
                    bool asc = (i & k) == 0;
                    float va = sv[i], vp = sv[p];
                    int   ia = si[i], ip = si[p];
                    bool pre = (vp > va) || (vp == va && ip < ia);
                    if (asc == pre) {
                        sv[i] = vp; sv[p] = va;
                        si[i] = ip; si[p] = ia;
                    }
                }
            }
            __syncthreads();
        }
    }
    if (t < UU) g_Mtop[bh * UU + t] = si[t];
}

// ---------------------------------------------------------------------------
// K4: V_mean partials; 1024 blocks (bh x 32 L-chunks of 64), atomicAdd merge.
// ---------------------------------------------------------------------------
__global__ void k_vmean(const float* __restrict__ V) {
    int blk = blockIdx.x;
    int bh = blk >> 5, chn = blk & 31;
    int b = bh >> 3, h = bh & 7;
    int t = threadIdx.x;
    int d = t & 63, sub = t >> 6;
    float s = 0.f;
#pragma unroll 16
    for (int i = 0; i < 16; i++) {
        int l = chn * 64 + sub + i * 4;
        s += V[(((size_t)(b * LL + l)) * HH + h) * DD + d];
    }
    __shared__ float red[256];
    red[t] = s;
    __syncthreads();
    if (t < 64) {
        float tot = red[t] + red[t + 64] + red[t + 128] + red[t + 192];
        atomicAdd(&g_Vmean[bh * DD + t], tot * (1.0f / (float)LL));
    }
}

// ---------------------------------------------------------------------------
// K5: out[b,l,h,:] = V_mean[b,h,:] for all l.
// ---------------------------------------------------------------------------
__global__ void k_fill(float* __restrict__ out) {
    int i = blockIdx.x * blockDim.x + threadIdx.x;
    if (i >= BB * LL * HH * (DD / 4)) return;
    int q4  = i & 15;
    int row = i >> 4;
    int h = row & 7;
    int b = row >> 14;
    float4 vm = reinterpret_cast<const float4*>(g_Vmean)[((b << 3) + h) * (DD / 4) + q4];
    reinterpret_cast<float4*>(out)[i] = vm;
}

// ---------------------------------------------------------------------------
// K6a: split-K attention partials. Block = (b,h, key-chunk of 128), 256 thr.
// ---------------------------------------------------------------------------
#define QS_PITCH 66
#define KS_PITCH 66
#define S_PITCH  130
#define SH_FLOATS (UU*QS_PITCH + CH*KS_PITCH + CH*KS_PITCH + UU*S_PITCH)
#define SH_BYTES  (SH_FLOATS*4 + UU*4)

__global__ void k_attn_part(const float* __restrict__ Q, const float* __restrict__ K,
                            const float* __restrict__ V) {
    int ch = blockIdx.x & (NCH - 1);
    int bh = blockIdx.x >> 4;
    int b = bh >> 3, h = bh & 7;
    int t = threadIdx.x;

    extern __shared__ float sh[];
    float* Qs = sh;                          // [40][66]
    float* Ks = Qs + UU * QS_PITCH;          // [128][66]
    float* Vs = Ks + CH * KS_PITCH;          // [128][66]
    float* S  = Vs + CH * KS_PITCH;          // [40][130]
    int* sidx = (int*)(S + UU * S_PITCH);    // [40]

    if (t < UU) sidx[t] = g_Mtop[bh * UU + t];
    __syncthreads();

    for (int i = t; i < UU * (DD / 4); i += 256) {
        int j = i >> 4, q4 = i & 15;
        float4 v = *(const float4*)(Q + (((size_t)(b * LL + sidx[j])) * HH + h) * DD + q4 * 4);
        float* dst = Qs + j * QS_PITCH + q4 * 4;
        dst[0] = v.x; dst[1] = v.y; dst[2] = v.z; dst[3] = v.w;
    }
    int k0 = ch * CH;
    for (int i = t; i < CH * (DD / 4); i += 256) {
        int r = i >> 4, q4 = i & 15;
        size_t base = (((size_t)(b * LL + k0 + r)) * HH + h) * DD + q4 * 4;
        float4 kv = *(const float4*)(K + base);
        float4 vv = *(const float4*)(V + base);
        float* dk = Ks + r * KS_PITCH + q4 * 4;
        float* dv = Vs + r * KS_PITCH + q4 * 4;
        dk[0] = kv.x; dk[1] = kv.y; dk[2] = kv.z; dk[3] = kv.w;
        dv[0] = vv.x; dv[1] = vv.y; dv[2] = vv.z; dv[3] = vv.w;
    }
    __syncthreads();

    // ---- phase 1: S[j][k] = scale * dot(Qs[j], Ks[k]) ----
    {
        int kg = t & 31, jg = t >> 5;
        float acc[5][4];
#pragma unroll
        for (int jt = 0; jt < 5; jt++)
#pragma unroll
            for (int kt = 0; kt < 4; kt++) acc[jt][kt] = 0.f;
#pragma unroll 8
        for (int d = 0; d < DD; d++) {
            float qv[5], kv[4];
#pragma unroll
            for (int jt = 0; jt < 5; jt++) qv[jt] = Qs[(jg + 8 * jt) * QS_PITCH + d];
#pragma unroll
            for (int kt = 0; kt < 4; kt++) kv[kt] = Ks[(kg + 32 * kt) * KS_PITCH + d];
#pragma unroll
            for (int jt = 0; jt < 5; jt++)
#pragma unroll
                for (int kt = 0; kt < 4; kt++) acc[jt][kt] += qv[jt] * kv[kt];
        }
#pragma unroll
        for (int jt = 0; jt < 5; jt++)
#pragma unroll
            for (int kt = 0; kt < 4; kt++)
                S[(jg + 8 * jt) * S_PITCH + (kg + 32 * kt)] = acc[jt][kt] * SCALE;
    }
    __syncthreads();

    // ---- phase 2: per-row chunk softmax stats; S <- exp(S - m) ----
    {
        int lane = t & 31, w = t >> 5;
#pragma unroll
        for (int i = 0; i < 5; i++) {
            int j = w * 5 + i;
            float* row = S + j * S_PITCH;
            float v0 = row[lane], v1 = row[lane + 32], v2 = row[lane + 64], v3 = row[lane + 96];
            float m = fmaxf(fmaxf(v0, v1), fmaxf(v2, v3));
            for (int off = 16; off; off >>= 1) m = fmaxf(m, __shfl_xor_sync(0xffffffffu, m, off));
            float e0 = __expf(v0 - m), e1 = __expf(v1 - m);
            float e2 = __expf(v2 - m), e3 = __expf(v3 - m);
            row[lane] = e0; row[lane + 32] = e1; row[lane + 64] = e2; row[lane + 96] = e3;
            float s = e0 + e1 + e2 + e3;
            for (int off = 16; off; off >>= 1) s += __shfl_xor_sync(0xffffffffu, s, off);
            if (lane == 0) {
                g_pm[(bh * UU + j) * NCH + ch] = m;
                g_ps[(bh * UU + j) * NCH + ch] = s;
            }
        }
    }
    __syncthreads();

    // ---- phase 3: partial a[j][d] = sum_k exp * Vs[k][d] (float2 over k) ----
    {
        int d = t & 63, grp = t >> 6;
        float a[10];
#pragma unroll
        for (int jt = 0; jt < 10; jt++) a[jt] = 0.f;
#pragma unroll 2
        for (int k = 0; k < CH; k += 2) {
            float v0 = Vs[k * KS_PITCH + d];
            float v1 = Vs[(k + 1) * KS_PITCH + d];
#pragma unroll
            for (int jt = 0; jt < 10; jt++) {
                float2 sj = *(const float2*)(S + (grp * 10 + jt) * S_PITCH + k);
                a[jt] += sj.x * v0 + sj.y * v1;
            }
        }
#pragma unroll
        for (int jt = 0; jt < 10; jt++)
            g_pa[((bh * UU + grp * 10 + jt) * NCH + ch) * DD + d] = a[jt];
    }
}

// ---------------------------------------------------------------------------
// K6b: merge the 16 chunk partials per (b,h,u); write selected row (over fill).
// ---------------------------------------------------------------------------
__global__ void k_attn_merge(float* __restrict__ out) {
    int u  = blockIdx.x % UU;
    int bh = blockIdx.x / UU;
    int b = bh >> 3, h = bh & 7;
    int d = threadIdx.x;
    int base = (bh * UU + u) * NCH;
    float gm = -CUDART_INF_F;
#pragma unroll
    for (int c = 0; c < NCH; c++) gm = fmaxf(gm, g_pm[base + c]);
    float tot = 0.f, val = 0.f;
#pragma unroll
    for (int c = 0; c < NCH; c++) {
        float e = __expf(g_pm[base + c] - gm);
        tot += g_ps[base + c] * e;
        val += g_pa[(base + c) * DD + d] * e;
    }
    int lq = g_Mtop[bh * UU + u];
    out[(((size_t)(b * LL + lq)) * HH + h) * DD + d] = val / tot;
}

// ---------------------------------------------------------------------------
extern "C" void kernel_launch(void* const* d_in, const int* in_sizes, int n_in,
                              void* d_out, int out_size) {
    const float* Q = (const float*)d_in[0];
    const float* K = (const float*)d_in[1];
    const float* V = (const float*)d_in[2];
    float* out = (float*)d_out;

    cudaFuncSetAttribute(k_attn_part, cudaFuncAttributeMaxDynamicSharedMemorySize,
                         SH_BYTES);
    cudaFuncSetAttribute(k_sampleM4, cudaFuncAttributeMaxDynamicSharedMemorySize,
                         SMP_SH_BYTES);

    k_rng<<<(NEL + 255) / 256, 256>>>();
    k_count<<<LL / 256, 256>>>();
    k_rank<<<NEL / 256, 256>>>();
    k_sampleM4<<<BH * NCHB, 1024, SMP_SH_BYTES>>>(Q, K);
    k_topk<<<BH, 512>>>();
    k_vmean<<<BH * 32, 256>>>(V);
    k_fill<<<(BB * LL * HH * (DD / 4)) / 256, 256>>>(out);
    k_attn_part<<<BH * NCH, 256, SH_BYTES>>>(Q, K, V);
    k_attn_merge<<<BH * UU, DD>>>(out);
}